// round 16
// baseline (speedup 1.0000x reference)
#include <cuda_runtime.h>
#include <cstdint>

// EmbeddingLayer_7808250544915 — R16 (resubmit of R15; broker timeout):
// memset + sparse tail experiment.
//
// Y: [J=2048, E=2048, B=64] fp32 (1.074 GB); only e in [2035,2047]
// is nonzero (6.8 MB = 0.64%). Decompose into:
//   1. cudaMemsetAsync(d_out, 0, full)  — driver fill path
//   2. tail kernel writing only the 13 nonzero e-columns per j
// Tests whether the driver's fill engine beats our 7.07 TB/s STG
// stream (R4 kernel, stable 145.5-146.0us over 5 runs). Predicted
// neutral-to-slightly-worse (LTS cap is path-independent); revert to
// the frozen R4 kernel if no win.

constexpr int E_DIM = 2048;
constexpr int J_DIM = 2048;
constexpr int B_DIM = 64;
constexpr int NZ_E  = 13;                   // e in [2035, 2047]
constexpr unsigned NONZERO_E_START = E_DIM - NZ_E;  // 2035

// Nonzero float4s: J * 13 * (B/4) = 2048 * 13 * 16 = 425,984
constexpr unsigned NZ_F4 = (unsigned)J_DIM * NZ_E * (B_DIM / 4);

__global__ void tail_bits_kernel(const int* __restrict__ x,
                                 float4* __restrict__ out) {
    unsigned t = blockIdx.x * blockDim.x + threadIdx.x;
    if (t >= NZ_F4) return;

    // t -> (j, e_off, b4):  13*16 = 208 float4s per j
    unsigned j     = t / 208u;
    unsigned rem   = t - j * 208u;
    unsigned e_off = rem >> 4;              // 0..12
    unsigned b     = (rem & 15u) << 2;      // first of 4 batch lanes
    unsigned e     = NONZERO_E_START + e_off;
    int shift      = (E_DIM - 1) - (int)e;  // 12 - e_off, in [0,12]

    int v0 = 2 * __ldg(&x[(b + 0) * E_DIM + j]) + 1;
    int v1 = 2 * __ldg(&x[(b + 1) * E_DIM + j]) + 1;
    int v2 = 2 * __ldg(&x[(b + 2) * E_DIM + j]) + 1;
    int v3 = 2 * __ldg(&x[(b + 3) * E_DIM + j]) + 1;

    float4 val;
    val.x = (float)((v0 >> shift) & 1);
    val.y = (float)((v1 >> shift) & 1);
    val.z = (float)((v2 >> shift) & 1);
    val.w = (float)((v3 >> shift) & 1);

    // out float4 index: (j*E + e)*16 + (b/4)
    unsigned idx4 = ((j << 11) + e) * 16u + (rem & 15u);
    out[idx4] = val;
}

extern "C" void kernel_launch(void* const* d_in, const int* in_sizes, int n_in,
                              void* d_out, int out_size) {
    const int* x = (const int*)d_in[0];
    float4* out = (float4*)d_out;

    // 1) Bulk zero-fill via the driver's memset path (async, capturable).
    size_t bytes = (size_t)out_size * sizeof(float);  // 1,073,741,824
    cudaMemsetAsync(d_out, 0, bytes, 0);

    // 2) Sparse tail: write the 13 nonzero e-columns (6.8 MB).
    constexpr int THREADS = 256;
    unsigned blocks = (NZ_F4 + THREADS - 1) / THREADS;  // 1664
    tail_bits_kernel<<<blocks, THREADS>>>(x, out);
}